// round 11
// baseline (speedup 1.0000x reference)
#include <cuda_runtime.h>

#define BT   65536       // batch
#define KM   31          // DIM-1 stacked MLPs
#define BLK  128         // threads per main block; 2 rows/thread -> 256 rows/block

typedef unsigned long long ull;

// ---------------- scratch (device globals: allocation-free) ----------------
__device__ float g_xt[32 * BT];        // x transposed: g_xt[j*BT + b]
__device__ float g_wt[KM * 2048];      // pre-transposed weights, 2048-float slab per k
// slab layout (float offsets): W1T 0 (768) | B1 768 | W2T 792 | B2 1368 |
//                              W3T 1392 | B3 1968 | W4T 1992 | B4 2040

// ---------------- f32x2 helpers ----------------
__device__ __forceinline__ ull ffma2(ull a, ull b, ull c) {
    ull d; asm("fma.rn.f32x2 %0, %1, %2, %3;" : "=l"(d) : "l"(a), "l"(b), "l"(c)); return d;
}
__device__ __forceinline__ ull dup2(float a) {
    ull d; asm("mov.b64 %0, {%1, %1};" : "=l"(d) : "f"(a)); return d;
}
__device__ __forceinline__ void unpack2(ull v, float& lo, float& hi) {
    asm("mov.b64 {%0, %1}, %2;" : "=f"(lo), "=f"(hi) : "l"(v));
}
__device__ __forceinline__ float lrelu(float v) { return fmaxf(v, 0.2f * v); }

// ---------------- smem layout (float offsets) ----------------
#define XS   0            // x slice [j][r]: 32*256
#define WS   8192         // weight slab copy: 2048
#define SMF  10240

// 24->24 layer, weights read via uniform LDG.128 from GLOBAL (L1-cached),
// bias from smem. Same math as the smem version.
__device__ __forceinline__ void layer24g(const float* __restrict__ a0,
                                         const float* __restrict__ a1,
                                         const float* __restrict__ wtg,   // global
                                         const float* bias,               // smem
                                         float* __restrict__ o0,
                                         float* __restrict__ o1)
{
    ull acc0[12], acc1[12];
    const ull* bp = (const ull*)bias;
    #pragma unroll
    for (int p = 0; p < 12; ++p) { acc0[p] = bp[p]; acc1[p] = bp[p]; }
    #pragma unroll
    for (int h = 0; h < 24; ++h) {
        const ull pa = dup2(a0[h]);
        const ull pb = dup2(a1[h]);
        const double2* w = (const double2*)(wtg + h * 24);
        #pragma unroll
        for (int q = 0; q < 3; ++q) {
            const double2 v0 = __ldg(w + 2*q);
            const double2 v1 = __ldg(w + 2*q + 1);
            const ull wx0 = __double_as_longlong(v0.x);
            const ull wy0 = __double_as_longlong(v0.y);
            const ull wx1 = __double_as_longlong(v1.x);
            const ull wy1 = __double_as_longlong(v1.y);
            acc0[4*q]   = ffma2(wx0, pa, acc0[4*q]);
            acc1[4*q]   = ffma2(wx0, pb, acc1[4*q]);
            acc0[4*q+1] = ffma2(wy0, pa, acc0[4*q+1]);
            acc1[4*q+1] = ffma2(wy0, pb, acc1[4*q+1]);
            acc0[4*q+2] = ffma2(wx1, pa, acc0[4*q+2]);
            acc1[4*q+2] = ffma2(wx1, pb, acc1[4*q+2]);
            acc0[4*q+3] = ffma2(wy1, pa, acc0[4*q+3]);
            acc1[4*q+3] = ffma2(wy1, pb, acc1[4*q+3]);
        }
    }
    #pragma unroll
    for (int p = 0; p < 12; ++p) {
        float lo, hi;
        unpack2(acc0[p], lo, hi); o0[2*p] = lrelu(lo); o0[2*p+1] = lrelu(hi);
        unpack2(acc1[p], lo, hi); o1[2*p] = lrelu(lo); o1[2*p+1] = lrelu(hi);
    }
}

// ---------------- kernel 1: x transpose + leaf + log_det init + weight transpose ----------------
__global__ void prep_kernel(const float* __restrict__ x,
                            const float* __restrict__ p0,
                            const float* __restrict__ W1, const float* __restrict__ b1,
                            const float* __restrict__ W2, const float* __restrict__ b2,
                            const float* __restrict__ W3, const float* __restrict__ b3,
                            const float* __restrict__ W4, const float* __restrict__ b4,
                            float* __restrict__ out)
{
    __shared__ float tile[128 * 33];
    const int tid = threadIdx.x;

    if (blockIdx.x < 512) {
        // ---- x transpose block (128 rows) ----
        const int base = blockIdx.x * 128;
        #pragma unroll
        for (int i = 0; i < 4; ++i) {
            const int idx = tid + i * 256;
            const int r  = idx >> 3;
            const int jc = idx & 7;
            const float4 v = ((const float4*)x)[(size_t)(base + r) * 8 + jc];
            tile[r * 33 + 4*jc + 0] = v.x;
            tile[r * 33 + 4*jc + 1] = v.y;
            tile[r * 33 + 4*jc + 2] = v.z;
            tile[r * 33 + 4*jc + 3] = v.w;
        }
        __syncthreads();
        #pragma unroll
        for (int i = 0; i < 16; ++i) {
            const int idx = tid + i * 256;
            const int j = idx >> 7;
            const int r = idx & 127;
            g_xt[j * BT + base + r] = tile[r * 33 + j];
        }
        if (tid < 128) {
            const float s0 = p0[0];
            out[(size_t)(base + tid) * 32 + 31] = tile[tid * 33] * expf(s0) + p0[1];
            out[(size_t)BT * 32 + base + tid] = s0;   // log_det accumulator init
        }
    } else {
        // ---- weight transpose block (one k) ----
        const int k = blockIdx.x - 512;
        float* dst = g_wt + k * 2048;
        for (int i = tid; i < 768; i += 256) {
            const int h = i >> 5, j = i & 31;
            dst[j * 24 + h] = W1[k * 768 + i];
        }
        for (int i = tid; i < 576; i += 256)
            dst[792 + (i % 24) * 24 + (i / 24)] = W2[k * 576 + i];
        for (int i = tid; i < 576; i += 256)
            dst[1392 + (i % 24) * 24 + (i / 24)] = W3[k * 576 + i];
        for (int i = tid; i < 48; i += 256)
            dst[1992 + (i % 24) * 2 + (i / 24)] = W4[k * 48 + i];
        if (tid < 24) {
            dst[768 + tid]  = b1[k * 24 + tid];
            dst[1368 + tid] = b2[k * 24 + tid];
            dst[1968 + tid] = b3[k * 24 + tid];
        }
        if (tid < 2) dst[2040 + tid] = b4[k * 2 + tid];
    }
}

// ---------------- kernel 2: main — one (k, 256-row tile) per block ----------------
__global__ __launch_bounds__(BLK, 4)
void maf_main(float* __restrict__ out)
{
    __shared__ __align__(16) float sm[SMF];

    const int tid  = threadIdx.x;
    const int k    = blockIdx.y;
    const int base = blockIdx.x * 256;
    const float* slab = g_wt + k * 2048;

    // ---- stage x slice (cols 0..k+1, float4) + weight slab (plain float4 copy) ----
    {
        const int nx4 = (k + 2) * 64;
        const float4* gx = (const float4*)g_xt;
        const int b4i = base >> 2;
        for (int idx = tid; idx < nx4; idx += BLK) {
            const int j  = idx >> 6;
            const int r4 = idx & 63;
            ((float4*)(sm + XS))[idx] = gx[j * (BT / 4) + b4i + r4];
        }
        const float4* gw = (const float4*)slab;
        #pragma unroll
        for (int i = 0; i < 4; ++i)
            ((float4*)(sm + WS))[tid + i * BLK] = gw[tid + i * BLK];
    }
    __syncthreads();

    const float* sw = sm + WS;
    float a0[24], a1[24], c0[24], c1[24];

    // ---- layer 1: (k+1) -> 24, x + W1T from smem ----
    {
        ull acc0[12], acc1[12];
        const ull* bp = (const ull*)(sw + 768);
        #pragma unroll
        for (int p = 0; p < 12; ++p) { acc0[p] = bp[p]; acc1[p] = bp[p]; }
        for (int j = 0; j <= k; ++j) {
            const ull pa = dup2(sm[XS + j * 256 + tid]);
            const ull pb = dup2(sm[XS + j * 256 + tid + 128]);
            const ulonglong2* w = (const ulonglong2*)(sw + j * 24);
            #pragma unroll
            for (int q = 0; q < 6; ++q) {
                const ulonglong2 wq = w[q];
                acc0[2*q]   = ffma2(wq.x, pa, acc0[2*q]);
                acc1[2*q]   = ffma2(wq.x, pb, acc1[2*q]);
                acc0[2*q+1] = ffma2(wq.y, pa, acc0[2*q+1]);
                acc1[2*q+1] = ffma2(wq.y, pb, acc1[2*q+1]);
            }
        }
        #pragma unroll
        for (int p = 0; p < 12; ++p) {
            float lo, hi;
            unpack2(acc0[p], lo, hi); a0[2*p] = lrelu(lo); a0[2*p+1] = lrelu(hi);
            unpack2(acc1[p], lo, hi); a1[2*p] = lrelu(lo); a1[2*p+1] = lrelu(hi);
        }
    }

    // ---- layers 2 & 3: weights via uniform LDG from g_wt (L1-cached) ----
    layer24g(a0, a1, slab + 792,  sw + 1368, c0, c1);
    layer24g(c0, c1, slab + 1392, sw + 1968, a0, a1);

    // ---- layer 4: 24 -> (s, t), from smem ----
    ull st0 = *(const ull*)(sw + 2040);
    ull st1 = st0;
    #pragma unroll
    for (int h = 0; h < 24; ++h) {
        const ull w = ((const ull*)(sw + 1992))[h];
        st0 = ffma2(w, dup2(a0[h]), st0);
        st1 = ffma2(w, dup2(a1[h]), st1);
    }
    float s0, t0, s1, t1;
    unpack2(st0, s0, t0);
    unpack2(st1, s1, t1);

    // ---- outputs ----
    const int r0 = base + tid;
    const int r1 = base + tid + 128;
    const float xk0 = sm[XS + (k + 1) * 256 + tid];
    const float xk1 = sm[XS + (k + 1) * 256 + tid + 128];
    out[(size_t)r0 * 32 + (30 - k)] = xk0 * expf(s0) + t0;
    out[(size_t)r1 * 32 + (30 - k)] = xk1 * expf(s1) + t1;
    atomicAdd(out + (size_t)BT * 32 + r0, s0);
    atomicAdd(out + (size_t)BT * 32 + r1, s1);
}

extern "C" void kernel_launch(void* const* d_in, const int* in_sizes, int n_in,
                              void* d_out, int out_size)
{
    const float* x  = (const float*)d_in[0];
    const float* p0 = (const float*)d_in[1];
    const float* W1 = (const float*)d_in[2];
    const float* b1 = (const float*)d_in[3];
    const float* W2 = (const float*)d_in[4];
    const float* b2 = (const float*)d_in[5];
    const float* W3 = (const float*)d_in[6];
    const float* b3 = (const float*)d_in[7];
    const float* W4 = (const float*)d_in[8];
    const float* b4 = (const float*)d_in[9];
    float* out = (float*)d_out;

    prep_kernel<<<512 + KM, 256>>>(x, p0, W1, b1, W2, b2, W3, b3, W4, b4, out);
    maf_main<<<dim3(BT / 256, KM), BLK>>>(out);
}

// round 12
// speedup vs baseline: 1.3990x; 1.3990x over previous
#include <cuda_runtime.h>

#define BT   65536       // batch
#define KM   31          // DIM-1 stacked MLPs
#define BLK  128         // threads per main block; 2 rows/thread -> 256 rows/block

typedef unsigned long long ull;

// ---------------- scratch (device globals: allocation-free) ----------------
__device__ float g_xt[32 * BT];        // x transposed: g_xt[j*BT + b]
__device__ float g_wt[KM * 2048];      // pre-transposed weights, 2048-float slab per k
// slab layout (float offsets): W1T 0 (768) | B1 768 | W2T 792 | B2 1368 |
//                              W3T 1392 | B3 1968 | W4T 1992 | B4 2040

// ---------------- f32x2 helpers ----------------
__device__ __forceinline__ ull ffma2(ull a, ull b, ull c) {
    ull d; asm("fma.rn.f32x2 %0, %1, %2, %3;" : "=l"(d) : "l"(a), "l"(b), "l"(c)); return d;
}
__device__ __forceinline__ ull dup2(float a) {
    ull d; asm("mov.b64 %0, {%1, %1};" : "=l"(d) : "f"(a)); return d;
}
__device__ __forceinline__ void unpack2(ull v, float& lo, float& hi) {
    asm("mov.b64 {%0, %1}, %2;" : "=f"(lo), "=f"(hi) : "l"(v));
}
__device__ __forceinline__ float lrelu(float v) { return fmaxf(v, 0.2f * v); }

// ---------------- smem layout (float offsets) ----------------
#define XS   0            // x slice [j][r]: 32*256
#define WS   8192         // weight slab copy: 2048
#define SMF  10240

// 24->24 layer on a row-pair, weights transposed in smem (champion version)
__device__ __forceinline__ void layer24(const float* __restrict__ a0,
                                        const float* __restrict__ a1,
                                        const float* wt, const float* bias,
                                        float* __restrict__ o0,
                                        float* __restrict__ o1)
{
    ull acc0[12], acc1[12];
    const ull* bp = (const ull*)bias;
    #pragma unroll
    for (int p = 0; p < 12; ++p) { acc0[p] = bp[p]; acc1[p] = bp[p]; }
    #pragma unroll
    for (int h = 0; h < 24; ++h) {
        const ull pa = dup2(a0[h]);
        const ull pb = dup2(a1[h]);
        const ulonglong2* w = (const ulonglong2*)(wt + h * 24);
        #pragma unroll
        for (int q = 0; q < 6; ++q) {
            const ulonglong2 wq = w[q];
            acc0[2*q]   = ffma2(wq.x, pa, acc0[2*q]);
            acc1[2*q]   = ffma2(wq.x, pb, acc1[2*q]);
            acc0[2*q+1] = ffma2(wq.y, pa, acc0[2*q+1]);
            acc1[2*q+1] = ffma2(wq.y, pb, acc1[2*q+1]);
        }
    }
    #pragma unroll
    for (int p = 0; p < 12; ++p) {
        float lo, hi;
        unpack2(acc0[p], lo, hi); o0[2*p] = lrelu(lo); o0[2*p+1] = lrelu(hi);
        unpack2(acc1[p], lo, hi); o1[2*p] = lrelu(lo); o1[2*p+1] = lrelu(hi);
    }
}

// ---------------- kernel 1: x transpose + leaf + log_det init + weight transpose ----------------
__global__ void prep_kernel(const float* __restrict__ x,
                            const float* __restrict__ p0,
                            const float* __restrict__ W1, const float* __restrict__ b1,
                            const float* __restrict__ W2, const float* __restrict__ b2,
                            const float* __restrict__ W3, const float* __restrict__ b3,
                            const float* __restrict__ W4, const float* __restrict__ b4,
                            float* __restrict__ out)
{
    __shared__ float tile[128 * 33];
    const int tid = threadIdx.x;

    if (blockIdx.x < 512) {
        // ---- x transpose block (128 rows) ----
        const int base = blockIdx.x * 128;
        #pragma unroll
        for (int i = 0; i < 4; ++i) {
            const int idx = tid + i * 256;
            const int r  = idx >> 3;
            const int jc = idx & 7;
            const float4 v = ((const float4*)x)[(size_t)(base + r) * 8 + jc];
            tile[r * 33 + 4*jc + 0] = v.x;
            tile[r * 33 + 4*jc + 1] = v.y;
            tile[r * 33 + 4*jc + 2] = v.z;
            tile[r * 33 + 4*jc + 3] = v.w;
        }
        __syncthreads();
        #pragma unroll
        for (int i = 0; i < 16; ++i) {
            const int idx = tid + i * 256;
            const int j = idx >> 7;
            const int r = idx & 127;
            g_xt[j * BT + base + r] = tile[r * 33 + j];
        }
        if (tid < 128) {
            const float s0 = p0[0];
            out[(size_t)(base + tid) * 32 + 31] = tile[tid * 33] * expf(s0) + p0[1];
            out[(size_t)BT * 32 + base + tid] = s0;   // log_det accumulator init
        }
    } else {
        // ---- weight transpose block (one k) ----
        const int k = blockIdx.x - 512;
        float* dst = g_wt + k * 2048;
        for (int i = tid; i < 768; i += 256) {
            const int h = i >> 5, j = i & 31;
            dst[j * 24 + h] = W1[k * 768 + i];
        }
        for (int i = tid; i < 576; i += 256)
            dst[792 + (i % 24) * 24 + (i / 24)] = W2[k * 576 + i];
        for (int i = tid; i < 576; i += 256)
            dst[1392 + (i % 24) * 24 + (i / 24)] = W3[k * 576 + i];
        for (int i = tid; i < 48; i += 256)
            dst[1992 + (i % 24) * 2 + (i / 24)] = W4[k * 48 + i];
        if (tid < 24) {
            dst[768 + tid]  = b1[k * 24 + tid];
            dst[1368 + tid] = b2[k * 24 + tid];
            dst[1968 + tid] = b3[k * 24 + tid];
        }
        if (tid < 2) dst[2040 + tid] = b4[k * 2 + tid];
    }
}

// ---------------- kernel 2: main — one (k, 256-row tile) per block ----------------
__global__ __launch_bounds__(BLK, 4)
void maf_main(float* __restrict__ out)
{
    __shared__ __align__(16) float sm[SMF];

    const int tid  = threadIdx.x;
    const int k    = blockIdx.y;
    const int base = blockIdx.x * 256;

    // ---- stage x slice (cols 0..k+1, float4) + weight slab (branch-free float4 copy) ----
    {
        const int nx4 = (k + 2) * 64;
        const float4* gx = (const float4*)g_xt;
        const int b4i = base >> 2;
        for (int idx = tid; idx < nx4; idx += BLK) {
            const int j  = idx >> 6;
            const int r4 = idx & 63;
            ((float4*)(sm + XS))[idx] = gx[j * (BT / 4) + b4i + r4];
        }
        const float4* gw = (const float4*)(g_wt + k * 2048);
        #pragma unroll
        for (int i = 0; i < 4; ++i)
            ((float4*)(sm + WS))[tid + i * BLK] = gw[tid + i * BLK];
    }
    __syncthreads();

    const float* sw = sm + WS;
    float a0[24], a1[24], c0[24], c1[24];

    // ---- layer 1: (k+1) -> 24, x + W1T from smem ----
    {
        ull acc0[12], acc1[12];
        const ull* bp = (const ull*)(sw + 768);
        #pragma unroll
        for (int p = 0; p < 12; ++p) { acc0[p] = bp[p]; acc1[p] = bp[p]; }
        for (int j = 0; j <= k; ++j) {
            const ull pa = dup2(sm[XS + j * 256 + tid]);
            const ull pb = dup2(sm[XS + j * 256 + tid + 128]);
            const ulonglong2* w = (const ulonglong2*)(sw + j * 24);
            #pragma unroll
            for (int q = 0; q < 6; ++q) {
                const ulonglong2 wq = w[q];
                acc0[2*q]   = ffma2(wq.x, pa, acc0[2*q]);
                acc1[2*q]   = ffma2(wq.x, pb, acc1[2*q]);
                acc0[2*q+1] = ffma2(wq.y, pa, acc0[2*q+1]);
                acc1[2*q+1] = ffma2(wq.y, pb, acc1[2*q+1]);
            }
        }
        #pragma unroll
        for (int p = 0; p < 12; ++p) {
            float lo, hi;
            unpack2(acc0[p], lo, hi); a0[2*p] = lrelu(lo); a0[2*p+1] = lrelu(hi);
            unpack2(acc1[p], lo, hi); a1[2*p] = lrelu(lo); a1[2*p+1] = lrelu(hi);
        }
    }

    // ---- layers 2 & 3: weights from smem (champion path) ----
    layer24(a0, a1, sw + 792,  sw + 1368, c0, c1);
    layer24(c0, c1, sw + 1392, sw + 1968, a0, a1);

    // ---- layer 4: 24 -> (s, t), from smem ----
    ull st0 = *(const ull*)(sw + 2040);
    ull st1 = st0;
    #pragma unroll
    for (int h = 0; h < 24; ++h) {
        const ull w = ((const ull*)(sw + 1992))[h];
        st0 = ffma2(w, dup2(a0[h]), st0);
        st1 = ffma2(w, dup2(a1[h]), st1);
    }
    float s0, t0, s1, t1;
    unpack2(st0, s0, t0);
    unpack2(st1, s1, t1);

    // ---- outputs: z[:, 30-k] = x[:, k+1]*exp(s)+t ; s -> log_det via REDG ----
    const int r0 = base + tid;
    const int r1 = base + tid + 128;
    const float xk0 = sm[XS + (k + 1) * 256 + tid];
    const float xk1 = sm[XS + (k + 1) * 256 + tid + 128];
    out[(size_t)r0 * 32 + (30 - k)] = xk0 * expf(s0) + t0;
    out[(size_t)r1 * 32 + (30 - k)] = xk1 * expf(s1) + t1;
    atomicAdd(out + (size_t)BT * 32 + r0, s0);
    atomicAdd(out + (size_t)BT * 32 + r1, s1);
}

extern "C" void kernel_launch(void* const* d_in, const int* in_sizes, int n_in,
                              void* d_out, int out_size)
{
    const float* x  = (const float*)d_in[0];
    const float* p0 = (const float*)d_in[1];
    const float* W1 = (const float*)d_in[2];
    const float* b1 = (const float*)d_in[3];
    const float* W2 = (const float*)d_in[4];
    const float* b2 = (const float*)d_in[5];
    const float* W3 = (const float*)d_in[6];
    const float* b3 = (const float*)d_in[7];
    const float* W4 = (const float*)d_in[8];
    const float* b4 = (const float*)d_in[9];
    float* out = (float*)d_out;

    prep_kernel<<<512 + KM, 256>>>(x, p0, W1, b1, W2, b2, W3, b3, W4, b4, out);
    maf_main<<<dim3(BT / 256, KM), BLK>>>(out);
}

// round 13
// speedup vs baseline: 1.4172x; 1.0130x over previous
#include <cuda_runtime.h>
#include <cstdint>

#define BT   65536       // batch
#define KM   31          // DIM-1 stacked MLPs
#define BLK  128         // threads; 2 rows/thread -> 256 rows/block
#define KCH  4           // k values per block (last chunk has 3)

typedef unsigned long long ull;

// ---------------- scratch (device globals: allocation-free) ----------------
__device__ float g_xt[32 * BT];        // x transposed: g_xt[j*BT + b]
__device__ float g_wt[KM * 2048];      // pre-transposed weight slab per k
// slab layout (float offsets): W1T 0 (768) | B1 768 | W2T 792 | B2 1368 |
//                              W3T 1392 | B3 1968 | W4T 1992 | B4 2040

// ---------------- f32x2 helpers ----------------
__device__ __forceinline__ ull ffma2(ull a, ull b, ull c) {
    ull d; asm("fma.rn.f32x2 %0, %1, %2, %3;" : "=l"(d) : "l"(a), "l"(b), "l"(c)); return d;
}
__device__ __forceinline__ ull dup2(float a) {
    ull d; asm("mov.b64 %0, {%1, %1};" : "=l"(d) : "f"(a)); return d;
}
__device__ __forceinline__ void unpack2(ull v, float& lo, float& hi) {
    asm("mov.b64 {%0, %1}, %2;" : "=f"(lo), "=f"(hi) : "l"(v));
}
__device__ __forceinline__ float lrelu(float v) { return fmaxf(v, 0.2f * v); }

__device__ __forceinline__ uint32_t smem_u32(const void* p) {
    uint32_t a;
    asm("{ .reg .u64 t; cvta.to.shared.u64 t, %1; cvt.u32.u64 %0, t; }" : "=r"(a) : "l"(p));
    return a;
}
__device__ __forceinline__ void cp16(uint32_t dst, const void* src) {
    asm volatile("cp.async.cg.shared.global [%0], [%1], 16;" :: "r"(dst), "l"(src));
}
__device__ __forceinline__ void cp_commit() {
    asm volatile("cp.async.commit_group;" ::: "memory");
}
template <int N>
__device__ __forceinline__ void cp_wait() {
    asm volatile("cp.async.wait_group %0;" :: "n"(N) : "memory");
}

// ---------------- smem layout (float offsets) ----------------
#define XS   0            // x slice [j][r]: 32*256 = 8192
#define WS   8192         // two weight slabs: 2*2048
#define SMF  (8192 + 2 * 2048)   // 12288 floats = 49152 B

// 24->24 layer on a row-pair, weights transposed in smem (champion version)
__device__ __forceinline__ void layer24(const float* __restrict__ a0,
                                        const float* __restrict__ a1,
                                        const float* wt, const float* bias,
                                        float* __restrict__ o0,
                                        float* __restrict__ o1)
{
    ull acc0[12], acc1[12];
    const ull* bp = (const ull*)bias;
    #pragma unroll
    for (int p = 0; p < 12; ++p) { acc0[p] = bp[p]; acc1[p] = bp[p]; }
    #pragma unroll
    for (int h = 0; h < 24; ++h) {
        const ull pa = dup2(a0[h]);
        const ull pb = dup2(a1[h]);
        const ulonglong2* w = (const ulonglong2*)(wt + h * 24);
        #pragma unroll
        for (int q = 0; q < 6; ++q) {
            const ulonglong2 wq = w[q];
            acc0[2*q]   = ffma2(wq.x, pa, acc0[2*q]);
            acc1[2*q]   = ffma2(wq.x, pb, acc1[2*q]);
            acc0[2*q+1] = ffma2(wq.y, pa, acc0[2*q+1]);
            acc1[2*q+1] = ffma2(wq.y, pb, acc1[2*q+1]);
        }
    }
    #pragma unroll
    for (int p = 0; p < 12; ++p) {
        float lo, hi;
        unpack2(acc0[p], lo, hi); o0[2*p] = lrelu(lo); o0[2*p+1] = lrelu(hi);
        unpack2(acc1[p], lo, hi); o1[2*p] = lrelu(lo); o1[2*p+1] = lrelu(hi);
    }
}

// ---------------- kernel 1: x transpose + leaf + log_det init + weight transpose ----------------
__global__ void prep_kernel(const float* __restrict__ x,
                            const float* __restrict__ p0,
                            const float* __restrict__ W1, const float* __restrict__ b1,
                            const float* __restrict__ W2, const float* __restrict__ b2,
                            const float* __restrict__ W3, const float* __restrict__ b3,
                            const float* __restrict__ W4, const float* __restrict__ b4,
                            float* __restrict__ out)
{
    __shared__ float tile[128 * 33];
    const int tid = threadIdx.x;

    if (blockIdx.x < 512) {
        const int base = blockIdx.x * 128;
        #pragma unroll
        for (int i = 0; i < 4; ++i) {
            const int idx = tid + i * 256;
            const int r  = idx >> 3;
            const int jc = idx & 7;
            const float4 v = ((const float4*)x)[(size_t)(base + r) * 8 + jc];
            tile[r * 33 + 4*jc + 0] = v.x;
            tile[r * 33 + 4*jc + 1] = v.y;
            tile[r * 33 + 4*jc + 2] = v.z;
            tile[r * 33 + 4*jc + 3] = v.w;
        }
        __syncthreads();
        #pragma unroll
        for (int i = 0; i < 16; ++i) {
            const int idx = tid + i * 256;
            const int j = idx >> 7;
            const int r = idx & 127;
            g_xt[j * BT + base + r] = tile[r * 33 + j];
        }
        if (tid < 128) {
            const float s0 = p0[0];
            out[(size_t)(base + tid) * 32 + 31] = tile[tid * 33] * expf(s0) + p0[1];
            out[(size_t)BT * 32 + base + tid] = s0;   // log_det accumulator init
        }
    } else {
        const int k = blockIdx.x - 512;
        float* dst = g_wt + k * 2048;
        for (int i = tid; i < 768; i += 256) {
            const int h = i >> 5, j = i & 31;
            dst[j * 24 + h] = W1[k * 768 + i];
        }
        for (int i = tid; i < 576; i += 256)
            dst[792 + (i % 24) * 24 + (i / 24)] = W2[k * 576 + i];
        for (int i = tid; i < 576; i += 256)
            dst[1392 + (i % 24) * 24 + (i / 24)] = W3[k * 576 + i];
        for (int i = tid; i < 48; i += 256)
            dst[1992 + (i % 24) * 2 + (i / 24)] = W4[k * 48 + i];
        if (tid < 24) {
            dst[768 + tid]  = b1[k * 24 + tid];
            dst[1368 + tid] = b2[k * 24 + tid];
            dst[1968 + tid] = b3[k * 24 + tid];
        }
        if (tid < 2) dst[2040 + tid] = b4[k * 2 + tid];
    }
}

// ---------------- kernel 2: main — one (tile, k-chunk) per block ----------------
__global__ __launch_bounds__(BLK, 4)
void maf_main(float* __restrict__ out)
{
    extern __shared__ __align__(16) float sm[];

    const int tid  = threadIdx.x;
    const int base = blockIdx.x * 256;
    const int k0   = blockIdx.y * KCH;
    const int k1   = (k0 + KCH < KM) ? (k0 + KCH) : KM;

    // ---- stage x slice once: cols 0..k1 (float4) ----
    {
        const int nx4 = (k1 + 1) * 64;
        const float4* gx = (const float4*)g_xt;
        const int b4i = base >> 2;
        for (int idx = tid; idx < nx4; idx += BLK) {
            const int j  = idx >> 6;
            const int r4 = idx & 63;
            ((float4*)(sm + XS))[idx] = gx[j * (BT / 4) + b4i + r4];
        }
    }

    // ---- prologue: cp.async slab k0 into buffer 0 ----
    const uint32_t ws_addr = smem_u32(sm + WS);
    {
        const float4* src = (const float4*)(g_wt + k0 * 2048);
        #pragma unroll
        for (int i = 0; i < 4; ++i) {
            const int idx = tid + i * BLK;
            cp16(ws_addr + idx * 16, src + idx);
        }
        cp_commit();
    }

    for (int k = k0; k < k1; ++k) {
        const int cur = (k - k0) & 1;

        // prefetch next slab into the other buffer
        if (k + 1 < k1) {
            const float4* src = (const float4*)(g_wt + (k + 1) * 2048);
            const uint32_t dst = ws_addr + (1 - cur) * 2048 * 4;
            #pragma unroll
            for (int i = 0; i < 4; ++i) {
                const int idx = tid + i * BLK;
                cp16(dst + idx * 16, src + idx);
            }
            cp_commit();
            cp_wait<1>();           // current slab complete; prefetch in flight
        } else {
            cp_wait<0>();
        }
        __syncthreads();            // slab (and x on first iter) visible to all

        const float* sw = sm + WS + cur * 2048;
        float a0[24], a1[24], c0[24], c1[24];

        // ---- layer 1: (k+1) -> 24 ----
        {
            ull acc0[12], acc1[12];
            const ull* bp = (const ull*)(sw + 768);
            #pragma unroll
            for (int p = 0; p < 12; ++p) { acc0[p] = bp[p]; acc1[p] = bp[p]; }
            #pragma unroll 2
            for (int j = 0; j <= k; ++j) {
                const ull pa = dup2(sm[XS + j * 256 + tid]);
                const ull pb = dup2(sm[XS + j * 256 + tid + 128]);
                const ulonglong2* w = (const ulonglong2*)(sw + j * 24);
                #pragma unroll
                for (int q = 0; q < 6; ++q) {
                    const ulonglong2 wq = w[q];
                    acc0[2*q]   = ffma2(wq.x, pa, acc0[2*q]);
                    acc1[2*q]   = ffma2(wq.x, pb, acc1[2*q]);
                    acc0[2*q+1] = ffma2(wq.y, pa, acc0[2*q+1]);
                    acc1[2*q+1] = ffma2(wq.y, pb, acc1[2*q+1]);
                }
            }
            #pragma unroll
            for (int p = 0; p < 12; ++p) {
                float lo, hi;
                unpack2(acc0[p], lo, hi); a0[2*p] = lrelu(lo); a0[2*p+1] = lrelu(hi);
                unpack2(acc1[p], lo, hi); a1[2*p] = lrelu(lo); a1[2*p+1] = lrelu(hi);
            }
        }

        // ---- layers 2 & 3 ----
        layer24(a0, a1, sw + 792,  sw + 1368, c0, c1);
        layer24(c0, c1, sw + 1392, sw + 1968, a0, a1);

        // ---- layer 4: 24 -> (s, t) ----
        ull st0 = *(const ull*)(sw + 2040);
        ull st1 = st0;
        #pragma unroll
        for (int h = 0; h < 24; ++h) {
            const ull w = ((const ull*)(sw + 1992))[h];
            st0 = ffma2(w, dup2(a0[h]), st0);
            st1 = ffma2(w, dup2(a1[h]), st1);
        }
        float s0, t0, s1, t1;
        unpack2(st0, s0, t0);
        unpack2(st1, s1, t1);

        // ---- outputs: z[:, 30-k] = x[:, k+1]*exp(s)+t ; s -> log_det via REDG ----
        const int r0 = base + tid;
        const int r1 = base + tid + 128;
        const float xk0 = sm[XS + (k + 1) * 256 + tid];
        const float xk1 = sm[XS + (k + 1) * 256 + tid + 128];
        out[(size_t)r0 * 32 + (30 - k)] = xk0 * expf(s0) + t0;
        out[(size_t)r1 * 32 + (30 - k)] = xk1 * expf(s1) + t1;
        atomicAdd(out + (size_t)BT * 32 + r0, s0);
        atomicAdd(out + (size_t)BT * 32 + r1, s1);

        __syncthreads();            // all reads of buf[cur] done before k+2 load reuses it
    }
}

extern "C" void kernel_launch(void* const* d_in, const int* in_sizes, int n_in,
                              void* d_out, int out_size)
{
    const float* x  = (const float*)d_in[0];
    const float* p0 = (const float*)d_in[1];
    const float* W1 = (const float*)d_in[2];
    const float* b1 = (const float*)d_in[3];
    const float* W2 = (const float*)d_in[4];
    const float* b2 = (const float*)d_in[5];
    const float* W3 = (const float*)d_in[6];
    const float* b3 = (const float*)d_in[7];
    const float* W4 = (const float*)d_in[8];
    const float* b4 = (const float*)d_in[9];
    float* out = (float*)d_out;

    const int smem_bytes = SMF * 4;
    cudaFuncSetAttribute(maf_main, cudaFuncAttributeMaxDynamicSharedMemorySize, smem_bytes);

    prep_kernel<<<512 + KM, 256>>>(x, p0, W1, b1, W2, b2, W3, b3, W4, b4, out);
    maf_main<<<dim3(BT / 256, (KM + KCH - 1) / KCH), BLK, smem_bytes>>>(out);
}